// round 16
// baseline (speedup 1.0000x reference)
#include <cuda_runtime.h>
#include <cuda_bf16.h>
#include <math.h>
#include <stdint.h>

#define BB   64
#define NE   500
#define NR   500
#define C1   151
#define CM   150
#define NEP  512
#define NRP  512
#define KP   160    // single-segment: A'=[ah], B'=[bh], [150,160)=0
#define KC   80     // k-chunk (bf16 elements)
#define NCH  2      // KP / KC
#define SP   88     // smem pitch (bf16) -> 176B rows
#define SPB  176
#define TE   64
#define TR   64
#define RBUF (64*SPB)     // per-buffer bytes (rs / ro / ent all 64 rows)

// ---------------- scratch (device globals; zero-init, pads never written) -----------
__device__ __nv_bfloat16 g_entB[BB][NEP][KP];  // bh
__device__ __nv_bfloat16 g_rsA [BB][NRP][KP];  // ah
__device__ __nv_bfloat16 g_roA [BB][NRP][KP];
__device__ float4 g_ent_box   [BB][NEP];
__device__ float4 g_epack     [BB][NEP];       // (ecx, ecy, score, sumsq)
__device__ float  g_earea     [BB][NEP];
__device__ float4 g_rs_box    [BB][NRP];
__device__ float4 g_ro_box    [BB][NRP];
__device__ float4 g_rel_vec   [BB][NRP];
__device__ float4 g_rpack     [BB][NRP];       // (sqS, sqO, areaRS, areaRO)

// ---------------- small helpers ------------------------------------------------------
__device__ __forceinline__ void warp_max2(float& a, float& b){
  #pragma unroll
  for (int o = 16; o; o >>= 1){
    float ta = __shfl_xor_sync(0xffffffffu, a, o);
    float tb = __shfl_xor_sync(0xffffffffu, b, o);
    a = fmaxf(a, ta); b = fmaxf(b, tb);
  }
}
__device__ __forceinline__ void warp_sum2(float& a, float& b){
  #pragma unroll
  for (int o = 16; o; o >>= 1){
    float ta = __shfl_xor_sync(0xffffffffu, a, o);
    float tb = __shfl_xor_sync(0xffffffffu, b, o);
    a += ta; b += tb;
  }
}
__device__ __forceinline__ uint32_t s2u(const void* p){
  uint32_t a;
  asm("{ .reg .u64 t; cvta.to.shared.u64 t, %1; cvt.u32.u64 %0, t; }" : "=r"(a) : "l"(p));
  return a;
}
__device__ __forceinline__ void ldsm_x4(uint32_t* r, uint32_t addr){
  asm volatile("ldmatrix.sync.aligned.m8n8.x4.shared.b16 {%0,%1,%2,%3}, [%4];"
    : "=r"(r[0]), "=r"(r[1]), "=r"(r[2]), "=r"(r[3]) : "r"(addr));
}
__device__ __forceinline__ void mma16816(float* d, const uint32_t* a, uint32_t b0, uint32_t b1){
  asm volatile("mma.sync.aligned.m16n8k16.row.col.f32.bf16.bf16.f32 "
    "{%0,%1,%2,%3}, {%4,%5,%6,%7}, {%8,%9}, {%0,%1,%2,%3};"
    : "+f"(d[0]), "+f"(d[1]), "+f"(d[2]), "+f"(d[3])
    : "r"(a[0]), "r"(a[1]), "r"(a[2]), "r"(a[3]), "r"(b0), "r"(b1));
}
__device__ __forceinline__ void cp16(uint32_t dst, const void* src){
  asm volatile("cp.async.cg.shared.global [%0], [%1], 16;" :: "r"(dst), "l"(src));
}
__device__ __forceinline__ void cp_commit(){ asm volatile("cp.async.commit_group;"); }
template<int N> __device__ __forceinline__ void cp_wait(){
  asm volatile("cp.async.wait_group %0;" :: "n"(N));
}

// ---------------- Phase 1 (merged): softmaxes -> bf16 rows ----------------------------
__device__ __forceinline__ void ent_block(const float* __restrict__ boxes,
                                          const float* __restrict__ logits,
                                          int b, int e0, float H, float W)
{
  int tid = threadIdx.x, warp = tid >> 5, lane = tid & 31;
  #pragma unroll
  for (int i = 0; i < 4; i++){
    int e = e0 + warp*4 + i;
    if (e >= NE) continue;
    const float* row = logits + ((size_t)b*NE + e)*C1;
    float v[5]; float mx = -INFINITY, mx150 = -INFINITY;
    #pragma unroll
    for (int j = 0; j < 5; j++){
      int k = lane + 32*j;
      v[j] = (k < C1) ? row[k] : -INFINITY;
      mx = fmaxf(mx, v[j]);
      if (k < CM) mx150 = fmaxf(mx150, v[j]);
    }
    warp_max2(mx, mx150);
    float s = 0.f, sq2 = 0.f;
    #pragma unroll
    for (int j = 0; j < 5; j++){
      int k = lane + 32*j;
      float ev = (k < C1) ? __expf(v[j] - mx) : 0.f;
      v[j] = ev; s += ev;
      if (k < CM) sq2 += ev*ev;
    }
    warp_sum2(s, sq2);
    float inv = __fdividef(1.f, s);
    __nv_bfloat16* dst = &g_entB[b][e][0];
    #pragma unroll
    for (int j = 0; j < 5; j++){
      int k = lane + 32*j;
      if (k < CM) dst[k] = __float2bfloat16(v[j]*inv);
    }
    if (lane == 0){
      const float* bx = boxes + ((size_t)b*NE + e)*4;
      float cx = bx[0], cy = bx[1], w = bx[2], h = bx[3];
      float x0 = (cx - 0.5f*w)*W, y0 = (cy - 0.5f*h)*H;
      float x1 = (cx + 0.5f*w)*W, y1 = (cy + 0.5f*h)*H;
      g_ent_box[b][e] = make_float4(x0, y0, x1, y1);
      g_epack[b][e]   = make_float4((x0 + x1)*0.5f, (y0 + y1)*0.5f,
                                    __expf(mx150 - mx) * inv, sq2*inv*inv);
      g_earea[b][e]   = (x1 - x0)*(y1 - y0);
    }
  }
}

__device__ __forceinline__ float rel_row(const float* __restrict__ row,
                                         __nv_bfloat16* __restrict__ dst, int lane)
{
  float v[5]; float mx = -INFINITY;
  #pragma unroll
  for (int j = 0; j < 5; j++){
    int k = lane + 32*j;
    v[j] = (k < C1) ? row[k] : -INFINITY;
    mx = fmaxf(mx, v[j]);
  }
  #pragma unroll
  for (int o = 16; o; o >>= 1) mx = fmaxf(mx, __shfl_xor_sync(0xffffffffu, mx, o));
  float s = 0.f, sq2 = 0.f;
  #pragma unroll
  for (int j = 0; j < 5; j++){
    int k = lane + 32*j;
    float ev = (k < C1) ? __expf(v[j] - mx) : 0.f;
    v[j] = ev; s += ev;
    if (k < CM) sq2 += ev*ev;
  }
  warp_sum2(s, sq2);
  float inv = __fdividef(1.f, s);
  #pragma unroll
  for (int j = 0; j < 5; j++){
    int k = lane + 32*j;
    if (k < CM) dst[k] = __float2bfloat16(v[j]*inv);
  }
  return sq2*inv*inv;
}

__device__ __forceinline__ void rel_block(const float* __restrict__ ro_logits,
                                          const float* __restrict__ rs_logits,
                                          const float* __restrict__ ro_box,
                                          const float* __restrict__ rs_box,
                                          const float* __restrict__ rel_vec,
                                          int b, int r0, float H, float W)
{
  int tid = threadIdx.x, warp = tid >> 5, lane = tid & 31;
  #pragma unroll
  for (int i = 0; i < 4; i++){
    int r = r0 + warp*4 + i;
    if (r >= NR) continue;
    size_t off = ((size_t)b*NR + r)*C1;
    float sq_s = rel_row(rs_logits + off, &g_rsA[b][r][0], lane);
    float sq_o = rel_row(ro_logits + off, &g_roA[b][r][0], lane);
    if (lane == 0){
      const float* bs = rs_box + ((size_t)b*NR + r)*4;
      float cx = bs[0], cy = bs[1], w = bs[2], h = bs[3];
      g_rs_box[b][r] = make_float4((cx-0.5f*w)*W, (cy-0.5f*h)*H,
                                   (cx+0.5f*w)*W, (cy+0.5f*h)*H);
      float aRS = (w*W)*(h*H);
      const float* bo = ro_box + ((size_t)b*NR + r)*4;
      cx = bo[0]; cy = bo[1]; w = bo[2]; h = bo[3];
      g_ro_box[b][r] = make_float4((cx-0.5f*w)*W, (cy-0.5f*h)*H,
                                   (cx+0.5f*w)*W, (cy+0.5f*h)*H);
      float aRO = (w*W)*(h*H);
      const float* rv = rel_vec + ((size_t)b*NR + r)*4;
      g_rel_vec[b][r] = make_float4(rv[0]*W, rv[1]*H, rv[2]*W, rv[3]*H);
      g_rpack[b][r]   = make_float4(sq_s, sq_o, aRS, aRO);
    }
  }
}

__global__ void phase1_kernel(const float* __restrict__ boxes,
                              const float* __restrict__ logits,
                              const float* __restrict__ ro_logits,
                              const float* __restrict__ rs_logits,
                              const float* __restrict__ ro_box,
                              const float* __restrict__ rs_box,
                              const float* __restrict__ rel_vec,
                              const float* __restrict__ tsizes)
{
  int b = blockIdx.y;
  float H = tsizes[2*b + 0], W = tsizes[2*b + 1];
  int bx = blockIdx.x;
  if (bx < 16) ent_block(boxes, logits, b, bx*32, H, W);
  else         rel_block(ro_logits, rs_logits, ro_box, rs_box, rel_vec,
                         b, (bx-16)*32, H, W);
}

// ---------------- Phase 2: 64x64 tile, 512 threads, 2 CTAs/SM (32 warps) -------------
struct SmemP2 {
  __nv_bfloat16 rs [2][TR][SP];    // 22 KB
  __nv_bfloat16 ro [2][TR][SP];    // 22 KB
  __nv_bfloat16 ent[2][TE][SP];    // 22 KB
  float4 ebox [TE];
  float4 epack[TE];
  float  earea[TE];
  float4 rsbox[TR];
  float4 robox[TR];
  float4 rvec [TR];
  float4 rpack[TR];
};

// fused pair-side; enclosing box via cw = (wE+wR) - iwu (exact identity, iwu unclamped)
__device__ __forceinline__ float pairval(float4 eb, float aE, float wE, float hE,
                                         float ecx, float ecy, float esc, float eq,
                                         float4 rb, float aR, float wR, float hR,
                                         float vx, float vy, float sqr, float dot)
{
  float ds = fabsf(vx - ecx) + fabsf(vy - ecy);
  float d2 = sqr + eq - 2.f*dot;
  float cd = sqrtf(fmaxf(d2, 1e-12f));
  float iwu = fminf(eb.z, rb.z) - fmaxf(eb.x, rb.x);
  float ihu = fminf(eb.w, rb.w) - fmaxf(eb.y, rb.y);
  float inter = fmaxf(iwu, 0.f) * fmaxf(ihu, 0.f);
  float cw = (wE + wR) - iwu;    // == max(ez,rz) - min(ex,rx), cw >= max(wE,wR) >= 0
  float ch = (hE + hR) - ihu;
  float uni = aE + aR - inter;
  float areaC = cw * ch;
  float num = esc * fmaf(inter, areaC, uni*(uni - areaC));
  float den = uni * areaC * (ds + 1.f) * (cd + 1.f);
  return fmaxf(num * __fdividef(1.f, den), 0.f);
}

// 3 x 64 rows x 10 x 16B = 1920 cp16 ops, ~4 per thread @512
__device__ __forceinline__ void load_chunk(uint32_t rsS, uint32_t roS, uint32_t entS,
                                           const __nv_bfloat16* grs,
                                           const __nv_bfloat16* gro,
                                           const __nv_bfloat16* gent,
                                           int buf, int c, int tid)
{
  #pragma unroll
  for (int it = 0; it < 4; it++){
    int idx = tid + it*512;
    if (idx >= 1920) break;
    int m   = idx / 640;
    int rem = idx - m*640;
    int row = rem / 10;
    int c16 = rem - row*10;
    uint32_t soff = (uint32_t)buf*RBUF + (uint32_t)row*SPB + c16*16;
    uint32_t dst  = (m == 0 ? rsS : m == 1 ? roS : entS) + soff;
    const __nv_bfloat16* base = (m == 0) ? grs : (m == 1) ? gro : gent;
    cp16(dst, base + (size_t)row*KP + (size_t)c*KC + c16*8);
  }
}

__global__ void __launch_bounds__(512, 2) phase2_kernel(float* __restrict__ out_s,
                                                        float* __restrict__ out_o)
{
  extern __shared__ char smem_raw[];
  SmemP2& sm = *reinterpret_cast<SmemP2*>(smem_raw);
  int b  = blockIdx.z;
  int e0 = blockIdx.x * TE;
  int r0 = blockIdx.y * TR;
  int tid = threadIdx.x;
  int lane = tid & 31, wid = tid >> 5;
  int wr = wid >> 2, we = wid & 3;          // 4x4 warp grid: 16r x 16e per warp
  int rbase = wr * 16, ebase = we * 16;

  const __nv_bfloat16* grs  = &g_rsA [b][r0][0];
  const __nv_bfloat16* gro  = &g_roA [b][r0][0];
  const __nv_bfloat16* gent = &g_entB[b][e0][0];
  uint32_t rsS  = s2u(&sm.rs [0][0][0]);
  uint32_t roS  = s2u(&sm.ro [0][0][0]);
  uint32_t entS = s2u(&sm.ent[0][0][0]);

  // epilogue scalar tiles (visible after first __syncthreads)
  if (tid < TE){
    int e = e0 + tid;
    sm.ebox[tid]  = g_ent_box[b][e];
    sm.epack[tid] = g_epack[b][e];
    sm.earea[tid] = g_earea[b][e];
  } else if (tid < TE + TR){
    int t = tid - TE;
    int r = r0 + t;
    sm.rsbox[t] = g_rs_box[b][r];
    sm.robox[t] = g_ro_box[b][r];
    sm.rvec[t]  = g_rel_vec[b][r];
    sm.rpack[t] = g_rpack[b][r];
  }

  // per-lane ldmatrix offsets (m16k16 A x4; n16k16 B x4)
  int aRow = rbase + ((lane >> 3) & 1)*8 + (lane & 7);
  int aColB = (lane >> 4) * 16;                       // bytes
  uint32_t aOff = (uint32_t)aRow*SPB + aColB;
  int bRow = ebase + ((lane >> 4) & 1)*8 + (lane & 7);
  int bColB = ((lane >> 3) & 1) * 16;
  uint32_t bOff = (uint32_t)bRow*SPB + bColB;

  float accS[2][4], accO[2][4];
  #pragma unroll
  for (int ni = 0; ni < 2; ni++)
    #pragma unroll
    for (int q = 0; q < 4; q++){ accS[ni][q] = 0.f; accO[ni][q] = 0.f; }

  load_chunk(rsS, roS, entS, grs, gro, gent, 0, 0, tid);
  cp_commit();

  for (int c = 0; c < NCH; c++){
    if (c + 1 < NCH){
      load_chunk(rsS, roS, entS, grs, gro, gent, (c+1)&1, c+1, tid);
      cp_commit();
      cp_wait<1>();
    } else {
      cp_wait<0>();
    }
    __syncthreads();

    uint32_t bB = (uint32_t)(c & 1) * RBUF;
    #pragma unroll
    for (int kk = 0; kk < 5; kk++){
      uint32_t kB = kk * 32;   // 16 bf16
      uint32_t a_rs[4], a_ro[4], bf[4];
      ldsm_x4(a_rs, rsS  + bB + aOff + kB);
      ldsm_x4(a_ro, roS  + bB + aOff + kB);
      ldsm_x4(bf,   entS + bB + bOff + kB);          // n8 tiles 0,1
      #pragma unroll
      for (int ni = 0; ni < 2; ni++){
        mma16816(accS[ni], a_rs, bf[ni*2], bf[ni*2+1]);
        mma16816(accO[ni], a_ro, bf[ni*2], bf[ni*2+1]);
      }
    }
    __syncthreads();
  }

  // ---- epilogue: ni outer (e-data hoisted for the 2-e pair), r streamed -----------
  int g = lane >> 2, t4 = lane & 3;
  #pragma unroll
  for (int ni = 0; ni < 2; ni++){
    int eloc = ebase + ni*8 + t4*2;
    int e = e0 + eloc;
    if (e >= NE) continue;            // NE even -> pair fully valid or fully invalid
    float4 eb0 = sm.ebox[eloc],  eb1 = sm.ebox[eloc+1];
    float4 ep0 = sm.epack[eloc], ep1 = sm.epack[eloc+1];
    float  aE0 = sm.earea[eloc], aE1 = sm.earea[eloc+1];
    float wE0 = eb0.z - eb0.x, hE0 = eb0.w - eb0.y;
    float wE1 = eb1.z - eb1.x, hE1 = eb1.w - eb1.y;
    #pragma unroll
    for (int rh = 0; rh < 2; rh++){
      int rloc = rbase + rh*8 + g;
      int r = r0 + rloc;
      if (r >= NR) continue;
      float4 rsb = sm.rsbox[rloc];
      float4 rob = sm.robox[rloc];
      float4 rv  = sm.rvec[rloc];
      float4 rp  = sm.rpack[rloc];   // (sqS, sqO, aRS, aRO)
      float wRS = rsb.z - rsb.x, hRS = rsb.w - rsb.y;
      float wRO = rob.z - rob.x, hRO = rob.w - rob.y;
      float oS0 = pairval(eb0, aE0, wE0, hE0, ep0.x, ep0.y, ep0.z, ep0.w,
                          rsb, rp.z, wRS, hRS, rv.x, rv.y, rp.x, accS[ni][rh*2+0]);
      float oS1 = pairval(eb1, aE1, wE1, hE1, ep1.x, ep1.y, ep1.z, ep1.w,
                          rsb, rp.z, wRS, hRS, rv.x, rv.y, rp.x, accS[ni][rh*2+1]);
      float oO0 = pairval(eb0, aE0, wE0, hE0, ep0.x, ep0.y, ep0.z, ep0.w,
                          rob, rp.w, wRO, hRO, rv.z, rv.w, rp.y, accO[ni][rh*2+0]);
      float oO1 = pairval(eb1, aE1, wE1, hE1, ep1.x, ep1.y, ep1.z, ep1.w,
                          rob, rp.w, wRO, hRO, rv.z, rv.w, rp.y, accO[ni][rh*2+1]);
      size_t base = ((size_t)b*NR + r)*NE + e;
      *(float2*)(out_s + base) = make_float2(oS0, oS1);
      *(float2*)(out_o + base) = make_float2(oO0, oO1);
    }
  }
}

// ---------------- launch --------------------------------------------------------------
extern "C" void kernel_launch(void* const* d_in, const int* in_sizes, int n_in,
                              void* d_out, int out_size)
{
  const float* pred_boxes  = (const float*)d_in[0];
  const float* pred_logits = (const float*)d_in[1];
  const float* ro_logits   = (const float*)d_in[2];
  const float* rs_logits   = (const float*)d_in[3];
  const float* ro_box      = (const float*)d_in[4];
  const float* rs_box      = (const float*)d_in[5];
  const float* rel_vec     = (const float*)d_in[6];
  const float* tsizes      = (const float*)d_in[7];
  float* out_s = (float*)d_out;
  float* out_o = out_s + (size_t)BB*NR*NE;

  static bool attr_set = false;
  if (!attr_set){
    cudaFuncSetAttribute(phase2_kernel, cudaFuncAttributeMaxDynamicSharedMemorySize,
                         (int)sizeof(SmemP2));
    attr_set = true;
  }

  dim3 g1(32, BB);
  phase1_kernel<<<g1, 256>>>(pred_boxes, pred_logits, ro_logits, rs_logits,
                             ro_box, rs_box, rel_vec, tsizes);
  dim3 g3(NEP / TE, NRP / TR, BB);
  phase2_kernel<<<g3, 512, sizeof(SmemP2)>>>(out_s, out_o);
}

// round 17
// speedup vs baseline: 1.1415x; 1.1415x over previous
#include <cuda_runtime.h>
#include <cuda_bf16.h>
#include <math.h>
#include <stdint.h>

#define BB   64
#define NE   500
#define NR   500
#define C1   151
#define CM   150
#define NEP  512
#define NRP  512
#define KP   160    // single-segment: A'=[ah], B'=[bh], [150,160)=0
#define KC   80     // k-chunk (bf16 elements)
#define NCH  2      // KP / KC
#define SP   88     // smem pitch (bf16) -> 176B rows
#define SPB  176
#define TE   64
#define TR   64
#define RBUF (64*SPB)     // per-buffer bytes (rs / ro / ent all 64 rows)

// ---------------- scratch (device globals; zero-init, pads never written) -----------
__device__ __nv_bfloat16 g_entB[BB][NEP][KP];  // bh
__device__ __nv_bfloat16 g_rsA [BB][NRP][KP];  // ah
__device__ __nv_bfloat16 g_roA [BB][NRP][KP];
__device__ float4 g_ent_box   [BB][NEP];
__device__ float4 g_epack     [BB][NEP];       // (ecx, ecy, score, sumsq)
__device__ float  g_earea     [BB][NEP];
__device__ float4 g_rs_box    [BB][NRP];
__device__ float4 g_ro_box    [BB][NRP];
__device__ float4 g_rel_vec   [BB][NRP];
__device__ float4 g_rpack     [BB][NRP];       // (sqS, sqO, areaRS, areaRO)

// ---------------- small helpers ------------------------------------------------------
__device__ __forceinline__ void warp_max2(float& a, float& b){
  #pragma unroll
  for (int o = 16; o; o >>= 1){
    float ta = __shfl_xor_sync(0xffffffffu, a, o);
    float tb = __shfl_xor_sync(0xffffffffu, b, o);
    a = fmaxf(a, ta); b = fmaxf(b, tb);
  }
}
__device__ __forceinline__ void warp_sum2(float& a, float& b){
  #pragma unroll
  for (int o = 16; o; o >>= 1){
    float ta = __shfl_xor_sync(0xffffffffu, a, o);
    float tb = __shfl_xor_sync(0xffffffffu, b, o);
    a += ta; b += tb;
  }
}
__device__ __forceinline__ uint32_t s2u(const void* p){
  uint32_t a;
  asm("{ .reg .u64 t; cvta.to.shared.u64 t, %1; cvt.u32.u64 %0, t; }" : "=r"(a) : "l"(p));
  return a;
}
__device__ __forceinline__ void ldsm_x4(uint32_t* r, uint32_t addr){
  asm volatile("ldmatrix.sync.aligned.m8n8.x4.shared.b16 {%0,%1,%2,%3}, [%4];"
    : "=r"(r[0]), "=r"(r[1]), "=r"(r[2]), "=r"(r[3]) : "r"(addr));
}
__device__ __forceinline__ void mma16816(float* d, const uint32_t* a, uint32_t b0, uint32_t b1){
  asm volatile("mma.sync.aligned.m16n8k16.row.col.f32.bf16.bf16.f32 "
    "{%0,%1,%2,%3}, {%4,%5,%6,%7}, {%8,%9}, {%0,%1,%2,%3};"
    : "+f"(d[0]), "+f"(d[1]), "+f"(d[2]), "+f"(d[3])
    : "r"(a[0]), "r"(a[1]), "r"(a[2]), "r"(a[3]), "r"(b0), "r"(b1));
}
__device__ __forceinline__ void cp16(uint32_t dst, const void* src){
  asm volatile("cp.async.cg.shared.global [%0], [%1], 16;" :: "r"(dst), "l"(src));
}
__device__ __forceinline__ void cp_commit(){ asm volatile("cp.async.commit_group;"); }
template<int N> __device__ __forceinline__ void cp_wait(){
  asm volatile("cp.async.wait_group %0;" :: "n"(N));
}

// ---------------- Phase 1 (merged): softmaxes -> bf16 rows, 1 row per warp ------------
__device__ __forceinline__ void ent_block(const float* __restrict__ boxes,
                                          const float* __restrict__ logits,
                                          int b, int e0, float H, float W)
{
  int tid = threadIdx.x, warp = tid >> 5, lane = tid & 31;
  int e = e0 + warp;
  if (e >= NE) return;
  const float* row = logits + ((size_t)b*NE + e)*C1;
  float v[5]; float mx = -INFINITY, mx150 = -INFINITY;
  #pragma unroll
  for (int j = 0; j < 5; j++){
    int k = lane + 32*j;
    v[j] = (k < C1) ? row[k] : -INFINITY;
    mx = fmaxf(mx, v[j]);
    if (k < CM) mx150 = fmaxf(mx150, v[j]);
  }
  warp_max2(mx, mx150);
  float s = 0.f, sq2 = 0.f;
  #pragma unroll
  for (int j = 0; j < 5; j++){
    int k = lane + 32*j;
    float ev = (k < C1) ? __expf(v[j] - mx) : 0.f;
    v[j] = ev; s += ev;
    if (k < CM) sq2 += ev*ev;
  }
  warp_sum2(s, sq2);
  float inv = __fdividef(1.f, s);
  __nv_bfloat16* dst = &g_entB[b][e][0];
  #pragma unroll
  for (int j = 0; j < 5; j++){
    int k = lane + 32*j;
    if (k < CM) dst[k] = __float2bfloat16(v[j]*inv);
  }
  if (lane == 0){
    const float* bx = boxes + ((size_t)b*NE + e)*4;
    float cx = bx[0], cy = bx[1], w = bx[2], h = bx[3];
    float x0 = (cx - 0.5f*w)*W, y0 = (cy - 0.5f*h)*H;
    float x1 = (cx + 0.5f*w)*W, y1 = (cy + 0.5f*h)*H;
    g_ent_box[b][e] = make_float4(x0, y0, x1, y1);
    g_epack[b][e]   = make_float4((x0 + x1)*0.5f, (y0 + y1)*0.5f,
                                  __expf(mx150 - mx) * inv, sq2*inv*inv);
    g_earea[b][e]   = (x1 - x0)*(y1 - y0);
  }
}

__device__ __forceinline__ float rel_row(const float* __restrict__ row,
                                         __nv_bfloat16* __restrict__ dst, int lane)
{
  float v[5]; float mx = -INFINITY;
  #pragma unroll
  for (int j = 0; j < 5; j++){
    int k = lane + 32*j;
    v[j] = (k < C1) ? row[k] : -INFINITY;
    mx = fmaxf(mx, v[j]);
  }
  #pragma unroll
  for (int o = 16; o; o >>= 1) mx = fmaxf(mx, __shfl_xor_sync(0xffffffffu, mx, o));
  float s = 0.f, sq2 = 0.f;
  #pragma unroll
  for (int j = 0; j < 5; j++){
    int k = lane + 32*j;
    float ev = (k < C1) ? __expf(v[j] - mx) : 0.f;
    v[j] = ev; s += ev;
    if (k < CM) sq2 += ev*ev;
  }
  warp_sum2(s, sq2);
  float inv = __fdividef(1.f, s);
  #pragma unroll
  for (int j = 0; j < 5; j++){
    int k = lane + 32*j;
    if (k < CM) dst[k] = __float2bfloat16(v[j]*inv);
  }
  return sq2*inv*inv;
}

__device__ __forceinline__ void rel_block(const float* __restrict__ ro_logits,
                                          const float* __restrict__ rs_logits,
                                          const float* __restrict__ ro_box,
                                          const float* __restrict__ rs_box,
                                          const float* __restrict__ rel_vec,
                                          int b, int r0, float H, float W)
{
  int tid = threadIdx.x, warp = tid >> 5, lane = tid & 31;
  int r = r0 + warp;
  if (r >= NR) return;
  size_t off = ((size_t)b*NR + r)*C1;
  float sq_s = rel_row(rs_logits + off, &g_rsA[b][r][0], lane);
  float sq_o = rel_row(ro_logits + off, &g_roA[b][r][0], lane);
  if (lane == 0){
    const float* bs = rs_box + ((size_t)b*NR + r)*4;
    float cx = bs[0], cy = bs[1], w = bs[2], h = bs[3];
    g_rs_box[b][r] = make_float4((cx-0.5f*w)*W, (cy-0.5f*h)*H,
                                 (cx+0.5f*w)*W, (cy+0.5f*h)*H);
    float aRS = (w*W)*(h*H);
    const float* bo = ro_box + ((size_t)b*NR + r)*4;
    cx = bo[0]; cy = bo[1]; w = bo[2]; h = bo[3];
    g_ro_box[b][r] = make_float4((cx-0.5f*w)*W, (cy-0.5f*h)*H,
                                 (cx+0.5f*w)*W, (cy+0.5f*h)*H);
    float aRO = (w*W)*(h*H);
    const float* rv = rel_vec + ((size_t)b*NR + r)*4;
    g_rel_vec[b][r] = make_float4(rv[0]*W, rv[1]*H, rv[2]*W, rv[3]*H);
    g_rpack[b][r]   = make_float4(sq_s, sq_o, aRS, aRO);
  }
}

#define ENT_BLKS 63   // ceil(500/8)
__global__ void phase1_kernel(const float* __restrict__ boxes,
                              const float* __restrict__ logits,
                              const float* __restrict__ ro_logits,
                              const float* __restrict__ rs_logits,
                              const float* __restrict__ ro_box,
                              const float* __restrict__ rs_box,
                              const float* __restrict__ rel_vec,
                              const float* __restrict__ tsizes)
{
  int b = blockIdx.y;
  float H = tsizes[2*b + 0], W = tsizes[2*b + 1];
  int bx = blockIdx.x;
  if (bx < ENT_BLKS) ent_block(boxes, logits, b, bx*8, H, W);
  else               rel_block(ro_logits, rs_logits, ro_box, rs_box, rel_vec,
                               b, (bx-ENT_BLKS)*8, H, W);
}

// ---------------- Phase 2: 64x64 tile, 256 threads, 3 CTAs/SM (round-15 form) --------
struct SmemP2 {
  __nv_bfloat16 rs [2][TR][SP];    // 22 KB
  __nv_bfloat16 ro [2][TR][SP];    // 22 KB
  __nv_bfloat16 ent[2][TE][SP];    // 22 KB
  float4 ebox [TE];
  float4 epack[TE];
  float  earea[TE];
  float4 rsbox[TR];
  float4 robox[TR];
  float4 rvec [TR];
  float4 rpack[TR];
};

// fused pair-side; enclosing box via cw = (wE+wR) - iwu (exact identity, iwu unclamped)
__device__ __forceinline__ float pairval(float4 eb, float aE, float wE, float hE,
                                         float ecx, float ecy, float esc, float eq,
                                         float4 rb, float aR, float wR, float hR,
                                         float vx, float vy, float sqr, float dot)
{
  float ds = fabsf(vx - ecx) + fabsf(vy - ecy);
  float d2 = sqr + eq - 2.f*dot;
  float cd = sqrtf(fmaxf(d2, 1e-12f));
  float iwu = fminf(eb.z, rb.z) - fmaxf(eb.x, rb.x);
  float ihu = fminf(eb.w, rb.w) - fmaxf(eb.y, rb.y);
  float inter = fmaxf(iwu, 0.f) * fmaxf(ihu, 0.f);
  float cw = (wE + wR) - iwu;    // == max(ez,rz) - min(ex,rx), cw >= max(wE,wR) >= 0
  float ch = (hE + hR) - ihu;
  float uni = aE + aR - inter;
  float areaC = cw * ch;
  float num = esc * fmaf(inter, areaC, uni*(uni - areaC));
  float den = uni * areaC * (ds + 1.f) * (cd + 1.f);
  return fmaxf(num * __fdividef(1.f, den), 0.f);
}

// 3 x 64 rows x 10 x 16B = 1920 cp16 ops, ~8 per thread @256
__device__ __forceinline__ void load_chunk(uint32_t rsS, uint32_t roS, uint32_t entS,
                                           const __nv_bfloat16* grs,
                                           const __nv_bfloat16* gro,
                                           const __nv_bfloat16* gent,
                                           int buf, int c, int tid)
{
  #pragma unroll
  for (int it = 0; it < 8; it++){
    int idx = tid + it*256;
    if (idx >= 1920) break;
    int m   = idx / 640;
    int rem = idx - m*640;
    int row = rem / 10;
    int c16 = rem - row*10;
    uint32_t soff = (uint32_t)buf*RBUF + (uint32_t)row*SPB + c16*16;
    uint32_t dst  = (m == 0 ? rsS : m == 1 ? roS : entS) + soff;
    const __nv_bfloat16* base = (m == 0) ? grs : (m == 1) ? gro : gent;
    cp16(dst, base + (size_t)row*KP + (size_t)c*KC + c16*8);
  }
}

__global__ void __launch_bounds__(256, 3) phase2_kernel(float* __restrict__ out_s,
                                                        float* __restrict__ out_o)
{
  extern __shared__ char smem_raw[];
  SmemP2& sm = *reinterpret_cast<SmemP2*>(smem_raw);
  int b  = blockIdx.z;
  int e0 = blockIdx.x * TE;
  int r0 = blockIdx.y * TR;
  int tid = threadIdx.x;
  int lane = tid & 31, wid = tid >> 5;
  int wr = wid >> 2, we = wid & 3;          // 2x4 warp grid: 32r x 16e per warp
  int rbase = wr * 32, ebase = we * 16;

  const __nv_bfloat16* grs  = &g_rsA [b][r0][0];
  const __nv_bfloat16* gro  = &g_roA [b][r0][0];
  const __nv_bfloat16* gent = &g_entB[b][e0][0];
  uint32_t rsS  = s2u(&sm.rs [0][0][0]);
  uint32_t roS  = s2u(&sm.ro [0][0][0]);
  uint32_t entS = s2u(&sm.ent[0][0][0]);

  // epilogue scalar tiles (visible after first __syncthreads)
  if (tid < TE){
    int e = e0 + tid;
    sm.ebox[tid]  = g_ent_box[b][e];
    sm.epack[tid] = g_epack[b][e];
    sm.earea[tid] = g_earea[b][e];
  } else if (tid < TE + TR){
    int t = tid - TE;
    int r = r0 + t;
    sm.rsbox[t] = g_rs_box[b][r];
    sm.robox[t] = g_ro_box[b][r];
    sm.rvec[t]  = g_rel_vec[b][r];
    sm.rpack[t] = g_rpack[b][r];
  }

  // per-lane ldmatrix offsets
  int aRow = rbase + ((lane >> 3) & 1)*8 + (lane & 7);
  int aColB = (lane >> 4) * 16;                       // bytes
  uint32_t aOff = (uint32_t)aRow*SPB + aColB;
  int bRow = ebase + ((lane >> 4) & 1)*8 + (lane & 7);
  int bColB = ((lane >> 3) & 1) * 16;
  uint32_t bOff = (uint32_t)bRow*SPB + bColB;

  float accS[2][2][4], accO[2][2][4];
  #pragma unroll
  for (int mi = 0; mi < 2; mi++)
    #pragma unroll
    for (int ni = 0; ni < 2; ni++)
      #pragma unroll
      for (int q = 0; q < 4; q++){ accS[mi][ni][q] = 0.f; accO[mi][ni][q] = 0.f; }

  load_chunk(rsS, roS, entS, grs, gro, gent, 0, 0, tid);
  cp_commit();

  for (int c = 0; c < NCH; c++){
    if (c + 1 < NCH){
      load_chunk(rsS, roS, entS, grs, gro, gent, (c+1)&1, c+1, tid);
      cp_commit();
      cp_wait<1>();
    } else {
      cp_wait<0>();
    }
    __syncthreads();

    uint32_t bB = (uint32_t)(c & 1) * RBUF;
    #pragma unroll
    for (int kk = 0; kk < 5; kk++){
      uint32_t kB = kk * 32;   // 16 bf16
      uint32_t a_rs[2][4], a_ro[2][4], bf[4];
      ldsm_x4(a_rs[0], rsS  + bB + aOff + kB);
      ldsm_x4(a_rs[1], rsS  + bB + aOff + 16*SPB + kB);
      ldsm_x4(a_ro[0], roS  + bB + aOff + kB);
      ldsm_x4(a_ro[1], roS  + bB + aOff + 16*SPB + kB);
      ldsm_x4(bf,      entS + bB + bOff + kB);          // n8 tiles 0,1
      #pragma unroll
      for (int mi = 0; mi < 2; mi++){
        #pragma unroll
        for (int ni = 0; ni < 2; ni++){
          mma16816(accS[mi][ni], a_rs[mi], bf[ni*2], bf[ni*2+1]);
          mma16816(accO[mi][ni], a_ro[mi], bf[ni*2], bf[ni*2+1]);
        }
      }
    }
    __syncthreads();
  }

  // ---- epilogue: ni outer (e-data hoisted for the 2-e pair), r streamed -----------
  int g = lane >> 2, t4 = lane & 3;
  #pragma unroll
  for (int ni = 0; ni < 2; ni++){
    int eloc = ebase + ni*8 + t4*2;
    int e = e0 + eloc;
    if (e >= NE) continue;            // NE even -> pair fully valid or fully invalid
    float4 eb0 = sm.ebox[eloc],  eb1 = sm.ebox[eloc+1];
    float4 ep0 = sm.epack[eloc], ep1 = sm.epack[eloc+1];
    float  aE0 = sm.earea[eloc], aE1 = sm.earea[eloc+1];
    float wE0 = eb0.z - eb0.x, hE0 = eb0.w - eb0.y;
    float wE1 = eb1.z - eb1.x, hE1 = eb1.w - eb1.y;
    #pragma unroll
    for (int mi = 0; mi < 2; mi++){
      #pragma unroll
      for (int rh = 0; rh < 2; rh++){
        int rloc = rbase + mi*16 + rh*8 + g;
        int r = r0 + rloc;
        if (r >= NR) continue;
        float4 rsb = sm.rsbox[rloc];
        float4 rob = sm.robox[rloc];
        float4 rv  = sm.rvec[rloc];
        float4 rp  = sm.rpack[rloc];   // (sqS, sqO, aRS, aRO)
        float wRS = rsb.z - rsb.x, hRS = rsb.w - rsb.y;
        float wRO = rob.z - rob.x, hRO = rob.w - rob.y;
        float oS0 = pairval(eb0, aE0, wE0, hE0, ep0.x, ep0.y, ep0.z, ep0.w,
                            rsb, rp.z, wRS, hRS, rv.x, rv.y, rp.x, accS[mi][ni][rh*2+0]);
        float oS1 = pairval(eb1, aE1, wE1, hE1, ep1.x, ep1.y, ep1.z, ep1.w,
                            rsb, rp.z, wRS, hRS, rv.x, rv.y, rp.x, accS[mi][ni][rh*2+1]);
        float oO0 = pairval(eb0, aE0, wE0, hE0, ep0.x, ep0.y, ep0.z, ep0.w,
                            rob, rp.w, wRO, hRO, rv.z, rv.w, rp.y, accO[mi][ni][rh*2+0]);
        float oO1 = pairval(eb1, aE1, wE1, hE1, ep1.x, ep1.y, ep1.z, ep1.w,
                            rob, rp.w, wRO, hRO, rv.z, rv.w, rp.y, accO[mi][ni][rh*2+1]);
        size_t base = ((size_t)b*NR + r)*NE + e;
        *(float2*)(out_s + base) = make_float2(oS0, oS1);
        *(float2*)(out_o + base) = make_float2(oO0, oO1);
      }
    }
  }
}

// ---------------- launch --------------------------------------------------------------
extern "C" void kernel_launch(void* const* d_in, const int* in_sizes, int n_in,
                              void* d_out, int out_size)
{
  const float* pred_boxes  = (const float*)d_in[0];
  const float* pred_logits = (const float*)d_in[1];
  const float* ro_logits   = (const float*)d_in[2];
  const float* rs_logits   = (const float*)d_in[3];
  const float* ro_box      = (const float*)d_in[4];
  const float* rs_box      = (const float*)d_in[5];
  const float* rel_vec     = (const float*)d_in[6];
  const float* tsizes      = (const float*)d_in[7];
  float* out_s = (float*)d_out;
  float* out_o = out_s + (size_t)BB*NR*NE;

  static bool attr_set = false;
  if (!attr_set){
    cudaFuncSetAttribute(phase2_kernel, cudaFuncAttributeMaxDynamicSharedMemorySize,
                         (int)sizeof(SmemP2));
    attr_set = true;
  }

  dim3 g1(2*ENT_BLKS, BB);
  phase1_kernel<<<g1, 256>>>(pred_boxes, pred_logits, ro_logits, rs_logits,
                             ro_box, rs_box, rel_vec, tsizes);
  dim3 g3(NEP / TE, NRP / TR, BB);
  phase2_kernel<<<g3, 256, sizeof(SmemP2)>>>(out_s, out_o);
}